// round 4
// baseline (speedup 1.0000x reference)
#include <cuda_runtime.h>
#include <math.h>

#define BZ   2
#define TT   2048
#define DD   1024
#define HH   16
#define DKK  64
#define DFF  4096
#define MM   (BZ*TT)          // 4096 rows total
#define AP   68               // padded attention smem row stride (floats)
#define ATTN_SMEM (4*64*AP*4) // Qs,Ks,Vs,Ps tiles: 69632 bytes

// ----------------------------------------------------------------------------
// Scratch (device globals — no runtime allocation allowed)
// ----------------------------------------------------------------------------
__device__ float g_h  [MM*DD];                 // LN output (reused for LN1 and LN2)
__device__ float g_q  [MM*DD];
__device__ float g_k  [MM*DD];
__device__ float g_v  [MM*DD];
__device__ float g_ctx[MM*DD];
__device__ float g_x2 [MM*DD];                 // x + attn (residual stream)
__device__ float g_act[(size_t)MM*DFF];        // GELU(fc1) activations

// ----------------------------------------------------------------------------
// LayerNorm: matches torch semantics — unbiased std (ddof=1), eps added to std
// out = (x - mean) * gamma / (std + eps) + beta
// One block per row, 256 threads x 4 elements (float4).
// ----------------------------------------------------------------------------
__global__ void __launch_bounds__(256) ln_kernel(const float* __restrict__ x,
        const float* __restrict__ g, const float* __restrict__ b,
        float* __restrict__ out)
{
    int row = blockIdx.x;
    int tid = threadIdx.x;
    const float* xr = x + (size_t)row * DD;
    float4 v = *reinterpret_cast<const float4*>(xr + tid*4);
    float s1 = v.x + v.y + v.z + v.w;
    float s2 = v.x*v.x + v.y*v.y + v.z*v.z + v.w*v.w;
    #pragma unroll
    for (int o = 16; o > 0; o >>= 1) {
        s1 += __shfl_xor_sync(0xffffffffu, s1, o);
        s2 += __shfl_xor_sync(0xffffffffu, s2, o);
    }
    __shared__ float r1[8], r2[8];
    __shared__ float sh_mean, sh_rstd;
    int wid = tid >> 5, lane = tid & 31;
    if (lane == 0) { r1[wid] = s1; r2[wid] = s2; }
    __syncthreads();
    if (tid == 0) {
        float a = 0.f, c = 0.f;
        #pragma unroll
        for (int i = 0; i < 8; i++) { a += r1[i]; c += r2[i]; }
        float mean = a * (1.0f / DD);
        float var  = (c - a * mean) * (1.0f / (DD - 1));   // unbiased
        var = fmaxf(var, 0.f);
        sh_mean = mean;
        sh_rstd = 1.0f / (sqrtf(var) + 1e-6f);             // eps added to STD
    }
    __syncthreads();
    float mean = sh_mean, rstd = sh_rstd;
    float4 gv = *reinterpret_cast<const float4*>(g + tid*4);
    float4 bv = *reinterpret_cast<const float4*>(b + tid*4);
    float4 ov;
    ov.x = (v.x - mean) * gv.x * rstd + bv.x;
    ov.y = (v.y - mean) * gv.y * rstd + bv.y;
    ov.z = (v.z - mean) * gv.z * rstd + bv.z;
    ov.w = (v.w - mean) * gv.w * rstd + bv.w;
    *reinterpret_cast<float4*>(out + (size_t)row*DD + tid*4) = ov;
}

// ----------------------------------------------------------------------------
// SGEMM: C[M,N] = A[M,K] @ B[K,N]  (+bias) (+exact GELU) (+residual)
// All row-major. M,N multiples of 128; K multiple of 16 (true for all calls).
// 128x128 block tile, BK=16, 256 threads, 8x8 per thread with split-tile
// (rows {ty*4, 64+ty*4}, cols {tx*4, 64+tx*4}) so smem reads are LDS.128
// conflict-free / broadcast.
// ----------------------------------------------------------------------------
template<bool GELU, bool RESID, bool BIAS>
__global__ void __launch_bounds__(256) sgemm_kernel(
        const float* __restrict__ A, const float* __restrict__ Bm,
        const float* __restrict__ bias, const float* __restrict__ resid,
        float* __restrict__ C, int M, int N, int K)
{
    __shared__ float As[16][128];   // transposed A tile: As[k][m]
    __shared__ float Bs[16][128];
    int tid = threadIdx.x;
    int tx = tid & 15, ty = tid >> 4;
    int brow = blockIdx.y * 128;
    int bcol = blockIdx.x * 128;

    int a_row = tid >> 2;           // 0..63 (plus +64 on second pass)
    int a_col = (tid & 3) << 2;     // 0,4,8,12
    int b_row = tid >> 5;           // 0..7  (plus +8)
    int b_col = (tid & 31) << 2;    // 0..124

    const float* Ag = A + (size_t)brow * K;
    const float* Bg = Bm + bcol;

    float acc[8][8];
    #pragma unroll
    for (int i = 0; i < 8; i++)
        #pragma unroll
        for (int j = 0; j < 8; j++) acc[i][j] = 0.f;

    for (int k0 = 0; k0 < K; k0 += 16) {
        #pragma unroll
        for (int u = 0; u < 2; u++) {
            int r = a_row + u*64;
            float4 va = *reinterpret_cast<const float4*>(Ag + (size_t)r*K + k0 + a_col);
            As[a_col+0][r] = va.x;
            As[a_col+1][r] = va.y;
            As[a_col+2][r] = va.z;
            As[a_col+3][r] = va.w;
        }
        #pragma unroll
        for (int u = 0; u < 2; u++) {
            int r = b_row + u*8;
            *reinterpret_cast<float4*>(&Bs[r][b_col]) =
                *reinterpret_cast<const float4*>(Bg + (size_t)(k0 + r)*N + b_col);
        }
        __syncthreads();
        #pragma unroll
        for (int k = 0; k < 16; k++) {
            float ra[8], rb[8];
            *reinterpret_cast<float4*>(&ra[0]) = *reinterpret_cast<const float4*>(&As[k][ty*4]);
            *reinterpret_cast<float4*>(&ra[4]) = *reinterpret_cast<const float4*>(&As[k][64 + ty*4]);
            *reinterpret_cast<float4*>(&rb[0]) = *reinterpret_cast<const float4*>(&Bs[k][tx*4]);
            *reinterpret_cast<float4*>(&rb[4]) = *reinterpret_cast<const float4*>(&Bs[k][64 + tx*4]);
            #pragma unroll
            for (int i = 0; i < 8; i++)
                #pragma unroll
                for (int j = 0; j < 8; j++)
                    acc[i][j] = fmaf(ra[i], rb[j], acc[i][j]);
        }
        __syncthreads();
    }

    #pragma unroll
    for (int i = 0; i < 8; i++) {
        int r = brow + ((i < 4) ? (ty*4 + i) : (60 + ty*4 + i));
        #pragma unroll
        for (int j = 0; j < 8; j++) {
            int c = bcol + ((j < 4) ? (tx*4 + j) : (60 + tx*4 + j));
            float val = acc[i][j];
            if (BIAS)  val += bias[c];
            if (GELU)  val = 0.5f * val * (1.0f + erff(val * 0.70710678118f)); // exact gelu
            if (RESID) val += resid[(size_t)r*N + c];
            C[(size_t)r*N + c] = val;
        }
    }
}

// ----------------------------------------------------------------------------
// Causal flash attention. q/k/v layout: [b, t, h, d] contiguous (GEMM output).
// One block = 64 query rows for one (b,h). 256 threads: thread = (row, cg);
// row = tid>>2 owns O[row][cg*16 .. cg*16+16). Online softmax with 4-thread
// shfl reductions across colgroups. Smem rows padded to AP=68 floats so
// stride-64 column walks are bank-conflict-free.
// ----------------------------------------------------------------------------
__global__ void __launch_bounds__(256) attn_kernel(const float* __restrict__ q,
        const float* __restrict__ k, const float* __restrict__ v,
        float* __restrict__ ctx)
{
    extern __shared__ float sm[];
    float* Qs = sm;
    float* Ks = sm + 64*AP;
    float* Vs = sm + 2*64*AP;
    float* Ps = sm + 3*64*AP;

    int qb = blockIdx.x, h = blockIdx.y, b = blockIdx.z;
    int tid = threadIdx.x;
    int row = tid >> 2, cg = tid & 3;
    const int ldg = HH * DKK;   // 1024

    const float* qbase = q + (size_t)(b*TT + qb*64) * ldg + h*DKK;
    const float* kbase = k + (size_t)(b*TT) * ldg + h*DKK;
    const float* vbase = v + (size_t)(b*TT) * ldg + h*DKK;

    #pragma unroll
    for (int j = 0; j < 4; j++)
        *reinterpret_cast<float4*>(&Qs[row*AP + cg*16 + j*4]) =
            *reinterpret_cast<const float4*>(qbase + (size_t)row*ldg + cg*16 + j*4);

    float m_i = -1e30f, l_i = 0.f;
    float o[16];
    #pragma unroll
    for (int j = 0; j < 16; j++) o[j] = 0.f;

    for (int kb = 0; kb <= qb; kb++) {
        __syncthreads();   // prior PV done (and Q visible on 1st iter path below)
        #pragma unroll
        for (int j = 0; j < 4; j++) {
            *reinterpret_cast<float4*>(&Ks[row*AP + cg*16 + j*4]) =
                *reinterpret_cast<const float4*>(kbase + (size_t)(kb*64+row)*ldg + cg*16 + j*4);
            *reinterpret_cast<float4*>(&Vs[row*AP + cg*16 + j*4]) =
                *reinterpret_cast<const float4*>(vbase + (size_t)(kb*64+row)*ldg + cg*16 + j*4);
        }
        __syncthreads();

        // S[row][c] for c in [cg*16, cg*16+16)
        float s[16];
        #pragma unroll
        for (int j = 0; j < 16; j++) s[j] = 0.f;
        #pragma unroll
        for (int d = 0; d < 64; d += 4) {
            float4 qv = *reinterpret_cast<const float4*>(&Qs[row*AP + d]);
            #pragma unroll
            for (int j = 0; j < 16; j++) {
                float4 kv = *reinterpret_cast<const float4*>(&Ks[(cg*16 + j)*AP + d]);
                s[j] = fmaf(qv.x, kv.x, fmaf(qv.y, kv.y, fmaf(qv.z, kv.z, fmaf(qv.w, kv.w, s[j]))));
            }
        }
        // scale by 1/sqrt(64); causal mask on diagonal tile
        if (kb == qb) {
            #pragma unroll
            for (int j = 0; j < 16; j++) {
                int kg = cg*16 + j;
                s[j] = (kg <= row) ? s[j] * 0.125f : -1e30f;
            }
        } else {
            #pragma unroll
            for (int j = 0; j < 16; j++) s[j] *= 0.125f;
        }

        // online softmax update (4-thread group per query row)
        float tmax = s[0];
        #pragma unroll
        for (int j = 1; j < 16; j++) tmax = fmaxf(tmax, s[j]);
        tmax = fmaxf(tmax, __shfl_xor_sync(0xffffffffu, tmax, 1));
        tmax = fmaxf(tmax, __shfl_xor_sync(0xffffffffu, tmax, 2));
        float m_new = fmaxf(m_i, tmax);
        float psum = 0.f;
        #pragma unroll
        for (int j = 0; j < 16; j++) {
            float p = __expf(s[j] - m_new);
            Ps[row*AP + cg*16 + j] = p;
            psum += p;
        }
        psum += __shfl_xor_sync(0xffffffffu, psum, 1);
        psum += __shfl_xor_sync(0xffffffffu, psum, 2);
        float corr = __expf(m_i - m_new);   // 0 on first tile (m_i = -1e30)
        l_i = l_i * corr + psum;
        m_i = m_new;
        #pragma unroll
        for (int j = 0; j < 16; j++) o[j] *= corr;
        __syncthreads();   // Ps visible to whole block

        // O[row][vc] += sum_kk P[row][kk] * V[kk][vc]
        for (int kk = 0; kk < 64; kk++) {
            float p = Ps[row*AP + kk];
            const float4 v0 = *reinterpret_cast<const float4*>(&Vs[kk*AP + cg*16 + 0]);
            const float4 v1 = *reinterpret_cast<const float4*>(&Vs[kk*AP + cg*16 + 4]);
            const float4 v2 = *reinterpret_cast<const float4*>(&Vs[kk*AP + cg*16 + 8]);
            const float4 v3 = *reinterpret_cast<const float4*>(&Vs[kk*AP + cg*16 + 12]);
            o[0]  = fmaf(p, v0.x, o[0]);  o[1]  = fmaf(p, v0.y, o[1]);
            o[2]  = fmaf(p, v0.z, o[2]);  o[3]  = fmaf(p, v0.w, o[3]);
            o[4]  = fmaf(p, v1.x, o[4]);  o[5]  = fmaf(p, v1.y, o[5]);
            o[6]  = fmaf(p, v1.z, o[6]);  o[7]  = fmaf(p, v1.w, o[7]);
            o[8]  = fmaf(p, v2.x, o[8]);  o[9]  = fmaf(p, v2.y, o[9]);
            o[10] = fmaf(p, v2.z, o[10]); o[11] = fmaf(p, v2.w, o[11]);
            o[12] = fmaf(p, v3.x, o[12]); o[13] = fmaf(p, v3.y, o[13]);
            o[14] = fmaf(p, v3.z, o[14]); o[15] = fmaf(p, v3.w, o[15]);
        }
    }

    float inv = 1.0f / l_i;
    float* ob = ctx + (size_t)(b*TT + qb*64 + row) * ldg + h*DKK + cg*16;
    float4 w0 = make_float4(o[0]*inv,  o[1]*inv,  o[2]*inv,  o[3]*inv);
    float4 w1 = make_float4(o[4]*inv,  o[5]*inv,  o[6]*inv,  o[7]*inv);
    float4 w2 = make_float4(o[8]*inv,  o[9]*inv,  o[10]*inv, o[11]*inv);
    float4 w3 = make_float4(o[12]*inv, o[13]*inv, o[14]*inv, o[15]*inv);
    *reinterpret_cast<float4*>(ob + 0)  = w0;
    *reinterpret_cast<float4*>(ob + 4)  = w1;
    *reinterpret_cast<float4*>(ob + 8)  = w2;
    *reinterpret_cast<float4*>(ob + 12) = w3;
}

// ----------------------------------------------------------------------------
// Launch: 9 kernels on the default stream (graph-capturable, no syncs/allocs).
// ----------------------------------------------------------------------------
extern "C" void kernel_launch(void* const* d_in, const int* in_sizes, int n_in,
                              void* d_out, int out_size)
{
    (void)in_sizes; (void)n_in; (void)out_size;
    const float* x     = (const float*)d_in[0];
    const float* w_q   = (const float*)d_in[1];
    const float* w_k   = (const float*)d_in[2];
    const float* w_v   = (const float*)d_in[3];
    const float* w_o   = (const float*)d_in[4];
    const float* b_o   = (const float*)d_in[5];
    const float* w_fc1 = (const float*)d_in[6];
    const float* b_fc1 = (const float*)d_in[7];
    const float* w_fc2 = (const float*)d_in[8];
    const float* b_fc2 = (const float*)d_in[9];
    const float* ln1_g = (const float*)d_in[10];
    const float* ln1_b = (const float*)d_in[11];
    const float* ln2_g = (const float*)d_in[12];
    const float* ln2_b = (const float*)d_in[13];
    float* out = (float*)d_out;

    static float *p_h, *p_q, *p_k, *p_v, *p_ctx, *p_x2, *p_act;
    static bool inited = []() {
        cudaGetSymbolAddress((void**)&p_h,   g_h);
        cudaGetSymbolAddress((void**)&p_q,   g_q);
        cudaGetSymbolAddress((void**)&p_k,   g_k);
        cudaGetSymbolAddress((void**)&p_v,   g_v);
        cudaGetSymbolAddress((void**)&p_ctx, g_ctx);
        cudaGetSymbolAddress((void**)&p_x2,  g_x2);
        cudaGetSymbolAddress((void**)&p_act, g_act);
        cudaFuncSetAttribute(attn_kernel,
                             cudaFuncAttributeMaxDynamicSharedMemorySize, ATTN_SMEM);
        return true;
    }();
    (void)inited;

    dim3 gD  (DD/128,  MM/128);   // (8, 32)  : N=1024 GEMMs
    dim3 gFF (DFF/128, MM/128);   // (32, 32) : N=4096 GEMM (fc1)
    dim3 gAtt(TT/64, HH, BZ);     // (32, 16, 2)

    // h = LN1(x)
    ln_kernel<<<MM, 256>>>(x, ln1_g, ln1_b, p_h);
    // q/k/v = h @ W_{q,k,v}   -> [b,t,h,d] layout
    sgemm_kernel<false,false,false><<<gD, 256>>>(p_h, w_q, nullptr, nullptr, p_q, MM, DD, DD);
    sgemm_kernel<false,false,false><<<gD, 256>>>(p_h, w_k, nullptr, nullptr, p_k, MM, DD, DD);
    sgemm_kernel<false,false,false><<<gD, 256>>>(p_h, w_v, nullptr, nullptr, p_v, MM, DD, DD);
    // ctx = causal softmax(qk^T/8) v
    attn_kernel<<<gAtt, 256, ATTN_SMEM>>>(p_q, p_k, p_v, p_ctx);
    // x2 = x + ctx @ W_o + b_o
    sgemm_kernel<false,true,true><<<gD, 256>>>(p_ctx, w_o, b_o, x, p_x2, MM, DD, DD);
    // h = LN2(x2)
    ln_kernel<<<MM, 256>>>(p_x2, ln2_g, ln2_b, p_h);
    // act = gelu(h @ W_fc1 + b_fc1)
    sgemm_kernel<true,false,true><<<gFF, 256>>>(p_h, w_fc1, b_fc1, nullptr, p_act, MM, DFF, DD);
    // out = x2 + act @ W_fc2 + b_fc2
    sgemm_kernel<false,true,true><<<gD, 256>>>(p_act, w_fc2, b_fc2, p_x2, out, MM, DD, DFF);
}

// round 7
// speedup vs baseline: 10.9714x; 10.9714x over previous
#include <cuda_runtime.h>
#include <cuda_fp16.h>
#include <stdint.h>
#include <math.h>

#define BZ   2
#define TT   2048
#define DD   1024
#define HH   16
#define DKK  64
#define DFF  4096
#define MM   (BZ*TT)          // 4096 rows total

// ----------------------------------------------------------------------------
// Scratch (device globals — no runtime allocation allowed)
// ----------------------------------------------------------------------------
__device__ __half g_h16 [MM*DD];                // LN output (fp16 GEMM A operand)
__device__ __half g_q16 [MM*DD];
__device__ __half g_k16 [MM*DD];
__device__ __half g_v16 [MM*DD];
__device__ __half g_ctx16[MM*DD];               // attention output (fp16)
__device__ float  g_x2  [MM*DD];                // x + attn (fp32 residual stream)
__device__ __half g_act16[(size_t)MM*DFF];      // GELU(fc1) activations (fp16)
// fp16 weight copies
__device__ __half g_wq16 [DD*DD];
__device__ __half g_wk16 [DD*DD];
__device__ __half g_wv16 [DD*DD];
__device__ __half g_wo16 [DD*DD];
__device__ __half g_wfc1_16[(size_t)DD*DFF];
__device__ __half g_wfc2_16[(size_t)DFF*DD];

// ----------------------------------------------------------------------------
// Baseline-PTX tensor-core helpers (sm_80-level: valid on compute_103)
// ----------------------------------------------------------------------------
__device__ __forceinline__ uint32_t smem_u32(const void* p) {
    uint32_t a;
    asm("{ .reg .u64 t; cvta.to.shared.u64 t, %1; cvt.u32.u64 %0, t; }" : "=r"(a) : "l"(p));
    return a;
}
__device__ __forceinline__ void ldsm_x4(uint32_t r[4], uint32_t a) {
    asm volatile("ldmatrix.sync.aligned.m8n8.x4.shared.b16 {%0,%1,%2,%3}, [%4];"
        : "=r"(r[0]), "=r"(r[1]), "=r"(r[2]), "=r"(r[3]) : "r"(a));
}
__device__ __forceinline__ void ldsm_x4_t(uint32_t r[4], uint32_t a) {
    asm volatile("ldmatrix.sync.aligned.m8n8.x4.trans.shared.b16 {%0,%1,%2,%3}, [%4];"
        : "=r"(r[0]), "=r"(r[1]), "=r"(r[2]), "=r"(r[3]) : "r"(a));
}
__device__ __forceinline__ void mma16816(float c[4], const uint32_t a[4], const uint32_t b[2]) {
    asm volatile("mma.sync.aligned.m16n8k16.row.col.f32.f16.f16.f32 "
        "{%0,%1,%2,%3}, {%4,%5,%6,%7}, {%8,%9}, {%0,%1,%2,%3};"
        : "+f"(c[0]), "+f"(c[1]), "+f"(c[2]), "+f"(c[3])
        : "r"(a[0]), "r"(a[1]), "r"(a[2]), "r"(a[3]), "r"(b[0]), "r"(b[1]));
}
#define CP_ASYNC16(dst, src) \
    asm volatile("cp.async.cg.shared.global [%0], [%1], 16;" :: "r"(dst), "l"(src))
#define CP_COMMIT() asm volatile("cp.async.commit_group;")
#define CP_WAIT1()  asm volatile("cp.async.wait_group 1;")
#define CP_WAIT0()  asm volatile("cp.async.wait_group 0;")

__device__ __forceinline__ uint32_t pack_h2(float a, float b) {
    __half2 h = __floats2half2_rn(a, b);
    return *reinterpret_cast<uint32_t*>(&h);
}

// ----------------------------------------------------------------------------
// fp32 -> fp16 conversion (weights)
// ----------------------------------------------------------------------------
__global__ void __launch_bounds__(256) cvt16_kernel(const float* __restrict__ s,
                                                    __half* __restrict__ d, int n)
{
    int i = (blockIdx.x * 256 + threadIdx.x) * 4;
    if (i < n) {
        float4 v = *reinterpret_cast<const float4*>(s + i);
        __align__(8) __half2 hv[2] = { __floats2half2_rn(v.x, v.y),
                                       __floats2half2_rn(v.z, v.w) };
        *reinterpret_cast<uint2*>(d + i) = *reinterpret_cast<uint2*>(hv);
    }
}

// ----------------------------------------------------------------------------
// LayerNorm (torch semantics: unbiased std ddof=1, eps added to std). fp16 out.
// ----------------------------------------------------------------------------
__global__ void __launch_bounds__(256) ln_kernel(const float* __restrict__ x,
        const float* __restrict__ g, const float* __restrict__ b,
        __half* __restrict__ out)
{
    int row = blockIdx.x;
    int tid = threadIdx.x;
    const float* xr = x + (size_t)row * DD;
    float4 v = *reinterpret_cast<const float4*>(xr + tid*4);
    float s1 = v.x + v.y + v.z + v.w;
    float s2 = v.x*v.x + v.y*v.y + v.z*v.z + v.w*v.w;
    #pragma unroll
    for (int o = 16; o > 0; o >>= 1) {
        s1 += __shfl_xor_sync(0xffffffffu, s1, o);
        s2 += __shfl_xor_sync(0xffffffffu, s2, o);
    }
    __shared__ float r1[8], r2[8];
    __shared__ float sh_mean, sh_rstd;
    int wid = tid >> 5, lane = tid & 31;
    if (lane == 0) { r1[wid] = s1; r2[wid] = s2; }
    __syncthreads();
    if (tid == 0) {
        float a = 0.f, c = 0.f;
        #pragma unroll
        for (int i = 0; i < 8; i++) { a += r1[i]; c += r2[i]; }
        float mean = a * (1.0f / DD);
        float var  = (c - a * mean) * (1.0f / (DD - 1));
        var = fmaxf(var, 0.f);
        sh_mean = mean;
        sh_rstd = 1.0f / (sqrtf(var) + 1e-6f);
    }
    __syncthreads();
    float mean = sh_mean, rstd = sh_rstd;
    float4 gv = *reinterpret_cast<const float4*>(g + tid*4);
    float4 bv = *reinterpret_cast<const float4*>(b + tid*4);
    float4 ov;
    ov.x = (v.x - mean) * gv.x * rstd + bv.x;
    ov.y = (v.y - mean) * gv.y * rstd + bv.y;
    ov.z = (v.z - mean) * gv.z * rstd + bv.z;
    ov.w = (v.w - mean) * gv.w * rstd + bv.w;
    __align__(8) __half2 hv[2] = { __floats2half2_rn(ov.x, ov.y),
                                   __floats2half2_rn(ov.z, ov.w) };
    *reinterpret_cast<uint2*>(out + (size_t)row*DD + tid*4) = *reinterpret_cast<uint2*>(hv);
}

// ----------------------------------------------------------------------------
// mma.sync fp16 GEMM: C[M,N] = A[M,K] @ B[K,N] (both row-major, fp16), fp32 acc.
// CTA 128x128, BK=32, 256 thr = 8 warps (2 along M x 4 along N; warp = 64x32).
// cp.async double-buffered smem. Padded strides: A 40 halves (80B), B 136
// halves (272B) -> conflict-free ldmatrix phases. Epilogue fuses bias/GELU/
// residual; fp32 or fp16 output. NB=3 fuses QKV via blockIdx.z.
// ----------------------------------------------------------------------------
#define ASTR 40
#define BSTR 136

template<bool GELU, bool RESID, bool BIAS, bool OUT16, int NB>
__global__ void __launch_bounds__(256) gemm_mma_kernel(
        const __half* __restrict__ A,
        const __half* __restrict__ B0, const __half* __restrict__ B1,
        const __half* __restrict__ B2,
        const float* __restrict__ bias, const float* __restrict__ resid,
        void* C0, void* C1, void* C2, int Kdim, int Ndim)
{
    __shared__ __align__(16) __half As[2][128*ASTR];
    __shared__ __align__(16) __half Bs[2][32*BSTR];

    int tid = threadIdx.x;
    int wid = tid >> 5, lane = tid & 31;
    int wm = wid & 1, wn = wid >> 1;

    const __half* B = B0;
    void* Cv = C0;
    if (NB == 3) {
        if (blockIdx.z == 1)      { B = B1; Cv = C1; }
        else if (blockIdx.z == 2) { B = B2; Cv = C2; }
    }

    int brow = blockIdx.y * 128;
    int bcol = blockIdx.x * 128;
    const __half* Ag = A + (size_t)brow * Kdim;
    const __half* Bg = B + bcol;

    float acc[4][4][4];
    #pragma unroll
    for (int mt = 0; mt < 4; mt++)
        #pragma unroll
        for (int nt = 0; nt < 4; nt++)
            #pragma unroll
            for (int e = 0; e < 4; e++) acc[mt][nt][e] = 0.f;

    auto load_tiles = [&](int buf, int k0) {
        uint32_t ab = smem_u32(&As[buf][0]);
        #pragma unroll
        for (int u = 0; u < 2; u++) {
            int c = tid + u * 256;
            int row = c >> 2, seg = c & 3;                  // 4x16B chunks / row
            CP_ASYNC16(ab + (row*ASTR + seg*8)*2,
                       Ag + (size_t)row * Kdim + k0 + seg*8);
        }
        uint32_t bb = smem_u32(&Bs[buf][0]);
        #pragma unroll
        for (int u = 0; u < 2; u++) {
            int c = tid + u * 256;
            int row = c >> 4, seg = c & 15;                 // 16x16B chunks / row
            CP_ASYNC16(bb + (row*BSTR + seg*8)*2,
                       Bg + (size_t)(k0 + row) * Ndim + seg*8);
        }
    };

    int nk = Kdim >> 5;
    load_tiles(0, 0);
    CP_COMMIT();

    int lrow = lane & 15, lcol = lane >> 4;

    for (int i = 0; i < nk; i++) {
        int buf = i & 1;
        if (i + 1 < nk) { load_tiles(buf ^ 1, (i + 1) << 5); CP_COMMIT(); CP_WAIT1(); }
        else            { CP_WAIT0(); }
        __syncthreads();

        uint32_t ab = smem_u32(&As[buf][0]);
        uint32_t bb = smem_u32(&Bs[buf][0]);
        #pragma unroll
        for (int ks = 0; ks < 2; ks++) {
            uint32_t af[4][4];
            #pragma unroll
            for (int mt = 0; mt < 4; mt++)
                ldsm_x4(af[mt], ab + ((wm*64 + mt*16 + lrow)*ASTR + ks*16 + lcol*8)*2);
            uint32_t bf[2][4];
            #pragma unroll
            for (int np = 0; np < 2; np++)
                ldsm_x4_t(bf[np], bb + ((ks*16 + lrow)*BSTR + wn*32 + np*16 + lcol*8)*2);
            #pragma unroll
            for (int mt = 0; mt < 4; mt++)
                #pragma unroll
                for (int nt = 0; nt < 4; nt++)
                    mma16816(acc[mt][nt], af[mt], &bf[nt >> 1][(nt & 1) * 2]);
        }
        __syncthreads();
    }

    // Epilogue: thread owns rows r0, r0+8; cols c0, c0+1 per (mt,nt)
    int r0 = brow + wm*64 + (lane >> 2);
    int c0 = bcol + wn*32 + (lane & 3) * 2;
    #pragma unroll
    for (int mt = 0; mt < 4; mt++) {
        #pragma unroll
        for (int hh = 0; hh < 2; hh++) {
            int r = r0 + mt*16 + hh*8;
            #pragma unroll
            for (int nt = 0; nt < 4; nt++) {
                int c = c0 + nt*8;
                float v0 = acc[mt][nt][hh*2 + 0];
                float v1 = acc[mt][nt][hh*2 + 1];
                if (BIAS) { v0 += bias[c]; v1 += bias[c + 1]; }
                if (GELU) {
                    v0 = 0.5f * v0 * (1.0f + erff(v0 * 0.70710678118f));
                    v1 = 0.5f * v1 * (1.0f + erff(v1 * 0.70710678118f));
                }
                if (RESID) {
                    v0 += resid[(size_t)r * Ndim + c];
                    v1 += resid[(size_t)r * Ndim + c + 1];
                }
                if (OUT16) {
                    __half2 hv = __floats2half2_rn(v0, v1);
                    *reinterpret_cast<__half2*>((__half*)Cv + (size_t)r * Ndim + c) = hv;
                } else {
                    *reinterpret_cast<float2*>((float*)Cv + (size_t)r * Ndim + c) =
                        make_float2(v0, v1);
                }
            }
        }
    }
}

// ----------------------------------------------------------------------------
// FA2-style causal attention via mma.sync. q/k/v fp16 [b,t,h*64+d].
// Block = 64 query rows of one (b,h); 128 thr = 4 warps; warp owns 16 rows.
// S = Q K^T (fp32 acc) -> online softmax in registers -> P (fp16, C-frag ->
// A-frag identity) -> O += P V (fp32 acc). Smem rows padded to 72 halves.
// ----------------------------------------------------------------------------
#define QSTR 72

__global__ void __launch_bounds__(128) attn_mma_kernel(
        const __half* __restrict__ q, const __half* __restrict__ k,
        const __half* __restrict__ v, __half* __restrict__ ctx)
{
    __shared__ __align__(16) __half Qs[64*QSTR];
    __shared__ __align__(16) __half Ks[64*QSTR];
    __shared__ __align__(16) __half Vs[64*QSTR];

    int qb = blockIdx.x, head = blockIdx.y, b = blockIdx.z;
    int tid = threadIdx.x, wid = tid >> 5, lane = tid & 31;
    const int ldg = HH * DKK;   // 1024

    const __half* qbase = q + (size_t)(b*TT + qb*64) * ldg + head*DKK;
    const __half* kbase = k + (size_t)(b*TT) * ldg + head*DKK;
    const __half* vbase = v + (size_t)(b*TT) * ldg + head*DKK;

    // Load Q tile (64 x 64 halves): 512 x 16B chunks, 4 per thread
    #pragma unroll
    for (int u = 0; u < 4; u++) {
        int c = tid + u * 128;
        int row = c >> 3, seg = c & 7;
        *reinterpret_cast<uint4*>(&Qs[row*QSTR + seg*8]) =
            *reinterpret_cast<const uint4*>(qbase + (size_t)row * ldg + seg*8);
    }
    __syncthreads();

    // Preload Q A-fragments (warp's 16 rows x k64 = 4 k-tiles)
    uint32_t qsb = smem_u32(Qs);
    int lrow = lane & 15, lcol = lane >> 4;
    uint32_t qf[4][4];
    #pragma unroll
    for (int kt = 0; kt < 4; kt++)
        ldsm_x4(qf[kt], qsb + ((wid*16 + lrow)*QSTR + kt*16 + lcol*8)*2);

    float m_i[2] = {-1e30f, -1e30f}, l_i[2] = {0.f, 0.f};
    float oacc[8][4];
    #pragma unroll
    for (int nt = 0; nt < 8; nt++)
        #pragma unroll
        for (int e = 0; e < 4; e++) oacc[nt][e] = 0.f;

    uint32_t ksb = smem_u32(Ks);
    uint32_t vsb = smem_u32(Vs);
    int qrow0 = qb*64 + wid*16 + (lane >> 2);   // thread rows: qrow0, qrow0+8

    for (int kb = 0; kb <= qb; kb++) {
        __syncthreads();
        #pragma unroll
        for (int u = 0; u < 4; u++) {
            int c = tid + u * 128;
            int row = c >> 3, seg = c & 7;
            *reinterpret_cast<uint4*>(&Ks[row*QSTR + seg*8]) =
                *reinterpret_cast<const uint4*>(kbase + (size_t)(kb*64 + row) * ldg + seg*8);
            *reinterpret_cast<uint4*>(&Vs[row*QSTR + seg*8]) =
                *reinterpret_cast<const uint4*>(vbase + (size_t)(kb*64 + row) * ldg + seg*8);
        }
        __syncthreads();

        // ---- S = Q K^T (K is [key][d] = col-major for mma -> non-trans) ----
        float sacc[8][4];
        #pragma unroll
        for (int nt = 0; nt < 8; nt++)
            #pragma unroll
            for (int e = 0; e < 4; e++) sacc[nt][e] = 0.f;

        #pragma unroll
        for (int kt = 0; kt < 4; kt++) {
            #pragma unroll
            for (int np = 0; np < 4; np++) {
                uint32_t bf[4];
                int nrow = np*16 + (lane & 7) + ((lane >= 16) ? 8 : 0);
                int koff = kt*16 + ((lane & 8) ? 8 : 0);
                ldsm_x4(bf, ksb + (nrow*QSTR + koff)*2);
                mma16816(sacc[np*2],     qf[kt], &bf[0]);
                mma16816(sacc[np*2 + 1], qf[kt], &bf[2]);
            }
        }

        // ---- scale + causal mask (diagonal tile only) ----
        if (kb == qb) {
            #pragma unroll
            for (int nt = 0; nt < 8; nt++) {
                int kcol = kb*64 + nt*8 + (lane & 3)*2;
                #pragma unroll
                for (int e = 0; e < 4; e++) {
                    int r = qrow0 + ((e >= 2) ? 8 : 0);
                    int c = kcol + (e & 1);
                    sacc[nt][e] = (c <= r) ? sacc[nt][e] * 0.125f : -1e30f;
                }
            }
        } else {
            #pragma unroll
            for (int nt = 0; nt < 8; nt++)
                #pragma unroll
                for (int e = 0; e < 4; e++) sacc[nt][e] *= 0.125f;
        }

        // ---- online softmax (rows: e<2 -> qrow0, e>=2 -> qrow0+8) ----
        float mx[2] = {-1e30f, -1e30f};
        #pragma unroll
        for (int nt = 0; nt < 8; nt++) {
            mx[0] = fmaxf(mx[0], fmaxf(sacc[nt][0], sacc[nt][1]));
            mx[1] = fmaxf(mx[1], fmaxf(sacc[nt][2], sacc[nt][3]));
        }
        #pragma unroll
        for (int hh = 0; hh < 2; hh++) {
            mx[hh] = fmaxf(mx[hh], __shfl_xor_sync(0xffffffffu, mx[hh], 1));
            mx[hh] = fmaxf(mx[hh], __shfl_xor_sync(0xffffffffu, mx[hh], 2));
        }
        float mnew[2] = { fmaxf(m_i[0], mx[0]), fmaxf(m_i[1], mx[1]) };
        float corr[2] = { __expf(m_i[0] - mnew[0]), __expf(m_i[1] - mnew[1]) };
        float ps[2] = {0.f, 0.f};
        #pragma unroll
        for (int nt = 0; nt < 8; nt++) {
            #pragma unroll
            for (int e = 0; e < 4; e++) {
                float p = __expf(sacc[nt][e] - mnew[(e >= 2) ? 1 : 0]);
                sacc[nt][e] = p;
                ps[(e >= 2) ? 1 : 0] += p;
            }
        }
        #pragma unroll
        for (int hh = 0; hh < 2; hh++) {
            ps[hh] += __shfl_xor_sync(0xffffffffu, ps[hh], 1);
            ps[hh] += __shfl_xor_sync(0xffffffffu, ps[hh], 2);
            l_i[hh] = l_i[hh] * corr[hh] + ps[hh];
            m_i[hh] = mnew[hh];
        }
        #pragma unroll
        for (int nt = 0; nt < 8; nt++) {
            oacc[nt][0] *= corr[0]; oacc[nt][1] *= corr[0];
            oacc[nt][2] *= corr[1]; oacc[nt][3] *= corr[1];
        }

        // ---- O += P V  (P: C-frag -> A-frag identity; V [kk][vc] -> .trans) ----
        #pragma unroll
        for (int kt = 0; kt < 4; kt++) {
            uint32_t pf[4];
            pf[0] = pack_h2(sacc[2*kt][0],     sacc[2*kt][1]);
            pf[1] = pack_h2(sacc[2*kt][2],     sacc[2*kt][3]);
            pf[2] = pack_h2(sacc[2*kt + 1][0], sacc[2*kt + 1][1]);
            pf[3] = pack_h2(sacc[2*kt + 1][2], sacc[2*kt + 1][3]);
            #pragma unroll
            for (int np = 0; np < 4; np++) {
                uint32_t bf[4];
                int krow = kt*16 + (lane & 15);
                int noff = np*16 + ((lane >= 16) ? 8 : 0);
                ldsm_x4_t(bf, vsb + (krow*QSTR + noff)*2);
                mma16816(oacc[np*2],     pf, &bf[0]);
                mma16816(oacc[np*2 + 1], pf, &bf[2]);
            }
        }
    }

    // ---- finalize: O /= l, write fp16 ctx ----
    float inv0 = 1.0f / l_i[0], inv1 = 1.0f / l_i[1];
    __half* ob = ctx + (size_t)(b*TT + qb*64 + wid*16 + (lane >> 2)) * ldg + head*DKK;
    #pragma unroll
    for (int nt = 0; nt < 8; nt++) {
        int col = nt*8 + (lane & 3)*2;
        *reinterpret_cast<__half2*>(ob + col) =
            __floats2half2_rn(oacc[nt][0]*inv0, oacc[nt][1]*inv0);
        *reinterpret_cast<__half2*>(ob + (size_t)8*ldg + col) =
            __floats2half2_rn(oacc[nt][2]*inv1, oacc[nt][3]*inv1);
    }
}

// ----------------------------------------------------------------------------
// Launch (graph-capturable: kernel launches only)
// ----------------------------------------------------------------------------
extern "C" void kernel_launch(void* const* d_in, const int* in_sizes, int n_in,
                              void* d_out, int out_size)
{
    (void)in_sizes; (void)n_in; (void)out_size;
    const float* x     = (const float*)d_in[0];
    const float* w_q   = (const float*)d_in[1];
    const float* w_k   = (const float*)d_in[2];
    const float* w_v   = (const float*)d_in[3];
    const float* w_o   = (const float*)d_in[4];
    const float* b_o   = (const float*)d_in[5];
    const float* w_fc1 = (const float*)d_in[6];
    const float* b_fc1 = (const float*)d_in[7];
    const float* w_fc2 = (const float*)d_in[8];
    const float* b_fc2 = (const float*)d_in[9];
    const float* ln1_g = (const float*)d_in[10];
    const float* ln1_b = (const float*)d_in[11];
    const float* ln2_g = (const float*)d_in[12];
    const float* ln2_b = (const float*)d_in[13];
    float* out = (float*)d_out;

    static __half *p_h16, *p_q16, *p_k16, *p_v16, *p_ctx16, *p_act16;
    static __half *p_wq16, *p_wk16, *p_wv16, *p_wo16, *p_wfc1_16, *p_wfc2_16;
    static float *p_x2;
    static bool inited = []() {
        cudaGetSymbolAddress((void**)&p_h16,     g_h16);
        cudaGetSymbolAddress((void**)&p_q16,     g_q16);
        cudaGetSymbolAddress((void**)&p_k16,     g_k16);
        cudaGetSymbolAddress((void**)&p_v16,     g_v16);
        cudaGetSymbolAddress((void**)&p_ctx16,   g_ctx16);
        cudaGetSymbolAddress((void**)&p_x2,      g_x2);
        cudaGetSymbolAddress((void**)&p_act16,   g_act16);
        cudaGetSymbolAddress((void**)&p_wq16,    g_wq16);
        cudaGetSymbolAddress((void**)&p_wk16,    g_wk16);
        cudaGetSymbolAddress((void**)&p_wv16,    g_wv16);
        cudaGetSymbolAddress((void**)&p_wo16,    g_wo16);
        cudaGetSymbolAddress((void**)&p_wfc1_16, g_wfc1_16);
        cudaGetSymbolAddress((void**)&p_wfc2_16, g_wfc2_16);
        return true;
    }();
    (void)inited;

    // Weight fp32 -> fp16 conversions
    cvt16_kernel<<<DD*DD/1024, 256>>>(w_q,   p_wq16,    DD*DD);
    cvt16_kernel<<<DD*DD/1024, 256>>>(w_k,   p_wk16,    DD*DD);
    cvt16_kernel<<<DD*DD/1024, 256>>>(w_v,   p_wv16,    DD*DD);
    cvt16_kernel<<<DD*DD/1024, 256>>>(w_o,   p_wo16,    DD*DD);
    cvt16_kernel<<<DD*DFF/1024, 256>>>(w_fc1, p_wfc1_16, DD*DFF);
    cvt16_kernel<<<DD*DFF/1024, 256>>>(w_fc2, p_wfc2_16, DFF*DD);

    dim3 gQKV(DD/128, MM/128, 3);   // (8, 32, 3)
    dim3 gD  (DD/128, MM/128);      // (8, 32)
    dim3 gFF (DFF/128, MM/128);     // (32, 32)
    dim3 gAtt(TT/64, HH, BZ);       // (32, 16, 2)

    // h = LN1(x)  (fp16)
    ln_kernel<<<MM, 256>>>(x, ln1_g, ln1_b, p_h16);
    // q/k/v = h @ W_{q,k,v}  (fp16 out, one fused launch)
    gemm_mma_kernel<false,false,false,true,3><<<gQKV, 256>>>(
        p_h16, p_wq16, p_wk16, p_wv16, nullptr, nullptr,
        p_q16, p_k16, p_v16, DD, DD);
    // ctx = causal softmax(q k^T / 8) v  (fp16 out)
    attn_mma_kernel<<<gAtt, 128>>>(p_q16, p_k16, p_v16, p_ctx16);
    // x2 = x + ctx @ W_o + b_o  (fp32 out)
    gemm_mma_kernel<false,true,true,false,1><<<gD, 256>>>(
        p_ctx16, p_wo16, nullptr, nullptr, b_o, x,
        p_x2, nullptr, nullptr, DD, DD);
    // h = LN2(x2)  (fp16)
    ln_kernel<<<MM, 256>>>(p_x2, ln2_g, ln2_b, p_h16);
    // act = gelu(h @ W_fc1 + b_fc1)  (fp16 out)
    gemm_mma_kernel<true,false,true,true,1><<<gFF, 256>>>(
        p_h16, p_wfc1_16, nullptr, nullptr, b_fc1, nullptr,
        p_act16, nullptr, nullptr, DD, DFF);
    // out = x2 + act @ W_fc2 + b_fc2  (fp32 out)
    gemm_mma_kernel<false,true,true,false,1><<<gD, 256>>>(
        p_act16, p_wfc2_16, nullptr, nullptr, b_fc2, p_x2,
        out, nullptr, nullptr, DFF, DD);
}